// round 13
// baseline (speedup 1.0000x reference)
#include <cuda_runtime.h>
#include <cuda_bf16.h>
#include <math.h>
#include <stdint.h>

#define T_DIM 1024
#define S_DIM 128
#define H_DIM 512
#define LN_EPS 1e-5f

#define KSPLIT 1536                 // 3 * 512: hi*hi + hi*lo + lo*hi
#define KCHUNK 64
#define NCHUNKS (KSPLIT / KCHUNK)   // 24
#define MT 64
#define NT 64
#define LDS_STRIDE 72               // bf16 per smem row (64 + 8 pad)
#define NSTAGE 4
#define A_STAGE_ELEMS (MT * LDS_STRIDE)
#define B_STAGE_ELEMS (NT * LDS_STRIDE)
#define SMEM_ELEMS (NSTAGE * (A_STAGE_ELEMS + B_STAGE_ELEMS))
#define SMEM_BYTES (SMEM_ELEMS * 2)

// Scratch (allocation-free rule: __device__ globals)
__device__ float d_gt[T_DIM * H_DIM];
__device__ float d_gs[S_DIM * H_DIM];
__device__ __nv_bfloat16 d_Abf[(T_DIM + S_DIM) * KSPLIT]; // [hi, hi, lo]
__device__ __nv_bfloat16 d_Wt[H_DIM * KSPLIT];            // wt: [hi, lo, hi]
__device__ __nv_bfloat16 d_Ws[H_DIM * KSPLIT];            // ws: [hi, lo, hi]

// ---------------------------------------------------------------------------
// cp.async helpers
// ---------------------------------------------------------------------------
__device__ __forceinline__ void cp_async16(uint32_t dst_smem, const void* src) {
    asm volatile("cp.async.cg.shared.global [%0], [%1], 16;"
                 :: "r"(dst_smem), "l"(src));
}
#define CP_COMMIT() asm volatile("cp.async.commit_group;" ::: "memory")
#define CP_WAIT(n)  asm volatile("cp.async.wait_group %0;" :: "n"(n) : "memory")

// ---------------------------------------------------------------------------
// Merged conversion
// ---------------------------------------------------------------------------
__global__ __launch_bounds__(256) void conv_kernel(
    const float* __restrict__ text, const float* __restrict__ sstruct,
    const float* __restrict__ W)
{
    const int b = blockIdx.x;
    if (b < T_DIM + S_DIM) {
        const int r = b;
        const float* src = (r < T_DIM) ? (text + (size_t)r * H_DIM)
                                       : (sstruct + (size_t)(r - T_DIM) * H_DIM);
        __nv_bfloat16* dst = d_Abf + (size_t)r * KSPLIT;
        for (int j = threadIdx.x; j < KSPLIT; j += 256) {
            int sec = j >> 9;
            int k   = j & 511;
            float x = src[k];
            __nv_bfloat16 h = __float2bfloat16(x);
            dst[j] = (sec == 2) ? __float2bfloat16(x - __bfloat162float(h)) : h;
        }
    } else {
        const int n = b - (T_DIM + S_DIM);
        const float* wrow = W + (size_t)n * 1024;
        __nv_bfloat16* dt = d_Wt + (size_t)n * KSPLIT;
        __nv_bfloat16* ds = d_Ws + (size_t)n * KSPLIT;
        for (int j = threadIdx.x; j < KSPLIT; j += 256) {
            int sec = j >> 9;
            int k   = j & 511;
            {
                float x = wrow[k];
                __nv_bfloat16 h = __float2bfloat16(x);
                dt[j] = (sec == 1) ? __float2bfloat16(x - __bfloat162float(h)) : h;
            }
            {
                float x = wrow[512 + k];
                __nv_bfloat16 h = __float2bfloat16(x);
                ds[j] = (sec == 1) ? __float2bfloat16(x - __bfloat162float(h)) : h;
            }
        }
    }
}

// ---------------------------------------------------------------------------
// HMMA GEMM with 4-deep cp.async ring.
// C[MT x NT] = A'[MT x 1536] @ B'[NT x 1536]^T, fp32 acc.
// 128 threads = 4 warps; warp (wm, wn) owns a 32x32 quadrant.
// Grid: 8 x 18 = 144 CTAs.  Dynamic smem = 73.7 KB.
// ---------------------------------------------------------------------------
__global__ __launch_bounds__(128) void mma_gemm_kernel()
{
    extern __shared__ __nv_bfloat16 smem[];

    const int tid  = threadIdx.x;
    const int wid  = tid >> 5;
    const int lane = tid & 31;
    const int wm   = wid & 1;
    const int wn   = wid >> 1;

    const int bcol  = blockIdx.x * NT;
    const int browg = blockIdx.y * MT;

    const __nv_bfloat16* __restrict__ Bsrc = (browg < T_DIM) ? d_Wt : d_Ws;
    float* __restrict__ C = (browg < T_DIM)
        ? (d_gt + (size_t)browg * H_DIM)
        : (d_gs + (size_t)(browg - T_DIM) * H_DIM);

    float acc[2][4][4];
    #pragma unroll
    for (int i = 0; i < 2; i++)
        #pragma unroll
        for (int j = 0; j < 4; j++)
            #pragma unroll
            for (int q = 0; q < 4; q++) acc[i][j][q] = 0.f;

    // Staging: 2 threads/row, each a contiguous 32-bf16 half-row (4 x 16B)
    const int srow  = tid >> 1;
    const int shalf = (tid & 1) * 32;

    const __nv_bfloat16* Aptr = d_Abf + (size_t)(browg + srow) * KSPLIT + shalf;
    const __nv_bfloat16* Bptr = Bsrc  + (size_t)(bcol  + srow) * KSPLIT + shalf;

    uint32_t sA[NSTAGE], sB[NSTAGE];
    #pragma unroll
    for (int st = 0; st < NSTAGE; st++) {
        sA[st] = (uint32_t)__cvta_generic_to_shared(
            smem + st * A_STAGE_ELEMS + srow * LDS_STRIDE + shalf);
        sB[st] = (uint32_t)__cvta_generic_to_shared(
            smem + NSTAGE * A_STAGE_ELEMS + st * B_STAGE_ELEMS
                 + srow * LDS_STRIDE + shalf);
    }

    // Prologue: prefetch chunks 0..2 into stages 0..2 (one group each)
    #pragma unroll
    for (int p = 0; p < 3; p++) {
        const __nv_bfloat16* ap = Aptr + (size_t)p * KCHUNK;
        const __nv_bfloat16* bp = Bptr + (size_t)p * KCHUNK;
        #pragma unroll
        for (int q = 0; q < 4; q++) {
            cp_async16(sA[p] + q * 16, ap + q * 8);
            cp_async16(sB[p] + q * 16, bp + q * 8);
        }
        CP_COMMIT();
    }

    const int frow = lane >> 2;
    const int fk   = (lane & 3) * 2;

    for (int c = 0; c < NCHUNKS; c++) {
        const int cur = c & (NSTAGE - 1);
        CP_WAIT(2);            // chunk c landed (c+1, c+2 may still be in flight)
        __syncthreads();       // cross-thread visibility of stage 'cur'

        const __nv_bfloat16 (*As)[LDS_STRIDE] =
            (const __nv_bfloat16 (*)[LDS_STRIDE])(smem + cur * A_STAGE_ELEMS);
        const __nv_bfloat16 (*Bs)[LDS_STRIDE] =
            (const __nv_bfloat16 (*)[LDS_STRIDE])(smem + NSTAGE * A_STAGE_ELEMS
                                                  + cur * B_STAGE_ELEMS);

        #pragma unroll
        for (int ks = 0; ks < KCHUNK; ks += 16) {
            uint32_t afr[2][4];
            #pragma unroll
            for (int mi = 0; mi < 2; mi++) {
                const int rb = wm * 32 + mi * 16;
                afr[mi][0] = *(const uint32_t*)&As[rb + frow    ][ks + fk    ];
                afr[mi][1] = *(const uint32_t*)&As[rb + frow + 8][ks + fk    ];
                afr[mi][2] = *(const uint32_t*)&As[rb + frow    ][ks + fk + 8];
                afr[mi][3] = *(const uint32_t*)&As[rb + frow + 8][ks + fk + 8];
            }
            #pragma unroll
            for (int ni = 0; ni < 4; ni++) {
                const int nb = wn * 32 + ni * 8;
                uint32_t b0 = *(const uint32_t*)&Bs[nb + frow][ks + fk    ];
                uint32_t b1 = *(const uint32_t*)&Bs[nb + frow][ks + fk + 8];
                #pragma unroll
                for (int mi = 0; mi < 2; mi++) {
                    asm volatile(
                        "mma.sync.aligned.m16n8k16.row.col.f32.bf16.bf16.f32 "
                        "{%0,%1,%2,%3}, {%4,%5,%6,%7}, {%8,%9}, {%0,%1,%2,%3};"
                        : "+f"(acc[mi][ni][0]), "+f"(acc[mi][ni][1]),
                          "+f"(acc[mi][ni][2]), "+f"(acc[mi][ni][3])
                        : "r"(afr[mi][0]), "r"(afr[mi][1]),
                          "r"(afr[mi][2]), "r"(afr[mi][3]),
                          "r"(b0), "r"(b1));
                }
            }
        }
        __syncthreads();       // readers done before this stage is refilled

        if (c + 3 < NCHUNKS) {
            const int nst = (c + 3) & (NSTAGE - 1);
            const __nv_bfloat16* ap = Aptr + (size_t)(c + 3) * KCHUNK;
            const __nv_bfloat16* bp = Bptr + (size_t)(c + 3) * KCHUNK;
            #pragma unroll
            for (int q = 0; q < 4; q++) {
                cp_async16(sA[nst] + q * 16, ap + q * 8);
                cp_async16(sB[nst] + q * 16, bp + q * 8);
            }
        }
        CP_COMMIT();           // may be an empty group (tail) — keeps counts aligned
    }

    #pragma unroll
    for (int mi = 0; mi < 2; mi++) {
        const int row = wm * 32 + mi * 16 + frow;
        #pragma unroll
        for (int ni = 0; ni < 4; ni++) {
            const int col = bcol + wn * 32 + ni * 8 + fk;
            *(float2*)(C + (size_t)row * H_DIM + col) =
                make_float2(acc[mi][ni][0], acc[mi][ni][1]);
            *(float2*)(C + (size_t)(row + 8) * H_DIM + col) =
                make_float2(acc[mi][ni][2], acc[mi][ni][3]);
        }
    }
}

// ---------------------------------------------------------------------------
// fuse2: store-only hot loop. TT=16, s-split across thread halves.
// Grid (16 h-chunks, 64 t-tiles) = 1024 CTAs, 256 threads, smem 34 KB
// -> 6 CTAs/SM (occ ~75%).
// ---------------------------------------------------------------------------
#define HC 32
#define TT 16

__global__ __launch_bounds__(256) void fuse2_kernel(
    const float* __restrict__ text,
    const float* __restrict__ sstruct,
    const int*   __restrict__ mask,
    const float* __restrict__ gate_b,
    float* __restrict__ xout,
    float* __restrict__ gates)
{
    __shared__ float gs_s[S_DIM][HC];
    __shared__ float st_s[S_DIM][HC];
    __shared__ float part[TT][8][4];

    const int tid = threadIdx.x;
    const int hx  = tid & 7;             // float4 within h-chunk
    const int ts  = (tid >> 3) & 15;     // row 0..15
    const int sh  = tid >> 7;            // 0..1 s-half
    const int h0  = blockIdx.x * HC;
    const int t0  = blockIdx.y * TT;

    #pragma unroll
    for (int i = tid; i < S_DIM * (HC / 4); i += 256) {
        int s  = i >> 3;
        int c4 = (i & 7) * 4;
        *(float4*)&gs_s[s][c4] = *(const float4*)(d_gs    + (size_t)s * H_DIM + h0 + c4);
        *(float4*)&st_s[s][c4] = *(const float4*)(sstruct + (size_t)s * H_DIM + h0 + c4);
    }
    __syncthreads();

    const int h = h0 + hx * 4;
    const int r = t0 + ts;

    const float4 bias = *(const float4*)(gate_b + h);
    float4 gtb;
    {
        float4 a = *(const float4*)(d_gt + (size_t)r * H_DIM + h);
        gtb = make_float4(a.x + bias.x, a.y + bias.y, a.z + bias.z, a.w + bias.w);
    }
    float4 acc = make_float4(0.f, 0.f, 0.f, 0.f);

    const int* __restrict__ mp = mask + (size_t)r * S_DIM;
    float* __restrict__ gp = gates + (size_t)r * S_DIM * H_DIM + h;

    const int s0 = sh * (S_DIM / 2);
    const int s1 = s0 + (S_DIM / 2);
    #pragma unroll 4
    for (int s = s0; s < s1; s++) {
        const float4 gs4 = *(const float4*)&gs_s[s][hx * 4];
        const float4 sv4 = *(const float4*)&st_s[s][hx * 4];
        const bool m = (mp[s] != 0);

        float4 g;
        g.x = m ? fmaxf(gtb.x + gs4.x, 0.f) : 0.f;
        g.y = m ? fmaxf(gtb.y + gs4.y, 0.f) : 0.f;
        g.z = m ? fmaxf(gtb.z + gs4.z, 0.f) : 0.f;
        g.w = m ? fmaxf(gtb.w + gs4.w, 0.f) : 0.f;

        __stcs((float4*)(gp + (size_t)s * H_DIM), g);

        acc.x = fmaf(g.x, sv4.x, acc.x);
        acc.y = fmaf(g.y, sv4.y, acc.y);
        acc.z = fmaf(g.z, sv4.z, acc.z);
        acc.w = fmaf(g.w, sv4.w, acc.w);
    }

    // Combine the two s-half partial enrichments, write x = text + enr.
    if (sh == 1) {
        part[ts][hx][0] = acc.x; part[ts][hx][1] = acc.y;
        part[ts][hx][2] = acc.z; part[ts][hx][3] = acc.w;
    }
    __syncthreads();
    if (sh == 0) {
        float4 t4 = *(const float4*)(text + (size_t)r * H_DIM + h);
        float4 x;
        x.x = t4.x + acc.x + part[ts][hx][0];
        x.y = t4.y + acc.y + part[ts][hx][1];
        x.z = t4.z + acc.z + part[ts][hx][2];
        x.w = t4.w + acc.w + part[ts][hx][3];
        *(float4*)(xout + (size_t)r * H_DIM + h) = x;
    }
}

// ---------------------------------------------------------------------------
// In-place LayerNorm. UNCHANGED.
// ---------------------------------------------------------------------------
__global__ __launch_bounds__(256) void ln_kernel(
    float* __restrict__ x,
    const float* __restrict__ gamma,
    const float* __restrict__ beta)
{
    const int tid = threadIdx.x;
    const int h4  = tid & 127;
    const int tg  = tid >> 7;
    const int h   = h4 * 4;
    const int r   = blockIdx.x * 2 + tg;

    __shared__ float red[2][2][4];

    float4 v = *(const float4*)(x + (size_t)r * H_DIM + h);
    float s1 = v.x + v.y + v.z + v.w;
    float s2 = v.x * v.x + v.y * v.y + v.z * v.z + v.w * v.w;

    const int lane = tid & 31;
    const int wg   = (tid >> 5) & 3;
    #pragma unroll
    for (int o = 16; o > 0; o >>= 1) {
        s1 += __shfl_xor_sync(0xFFFFFFFFu, s1, o);
        s2 += __shfl_xor_sync(0xFFFFFFFFu, s2, o);
    }
    if (lane == 0) { red[0][tg][wg] = s1; red[1][tg][wg] = s2; }
    __syncthreads();

    s1 = red[0][tg][0] + red[0][tg][1] + red[0][tg][2] + red[0][tg][3];
    s2 = red[1][tg][0] + red[1][tg][1] + red[1][tg][2] + red[1][tg][3];
    float mu  = s1 * (1.f / H_DIM);
    float var = s2 * (1.f / H_DIM) - mu * mu;
    float inv = rsqrtf(var + LN_EPS);

    const float4 gm = *(const float4*)(gamma + h);
    const float4 bt = *(const float4*)(beta  + h);
    float4 o;
    o.x = (v.x - mu) * inv * gm.x + bt.x;
    o.y = (v.y - mu) * inv * gm.y + bt.y;
    o.z = (v.z - mu) * inv * gm.z + bt.z;
    o.w = (v.w - mu) * inv * gm.w + bt.w;
    *(float4*)(x + (size_t)r * H_DIM + h) = o;
}

// ---------------------------------------------------------------------------
extern "C" void kernel_launch(void* const* d_in, const int* in_sizes, int n_in,
                              void* d_out, int out_size)
{
    const float* text    = (const float*)d_in[0];
    const float* sstruct = (const float*)d_in[1];
    const int*   mask    = (const int*)  d_in[2];
    const float* gate_w  = (const float*)d_in[3];
    const float* gate_b  = (const float*)d_in[4];
    const float* gamma   = (const float*)d_in[5];
    const float* beta    = (const float*)d_in[6];

    float* enriched = (float*)d_out;
    float* gates    = (float*)d_out + (size_t)T_DIM * H_DIM;

    conv_kernel<<<T_DIM + S_DIM + H_DIM, 256>>>(text, sstruct, gate_w);
    {
        cudaFuncSetAttribute(mma_gemm_kernel,
                             cudaFuncAttributeMaxDynamicSharedMemorySize,
                             SMEM_BYTES);
        dim3 grd(H_DIM / NT, (T_DIM + S_DIM) / MT);   // 8 x 18 = 144 CTAs
        mma_gemm_kernel<<<grd, 128, SMEM_BYTES>>>();
    }
    {
        dim3 grd(H_DIM / HC, T_DIM / TT);             // 16 x 64 = 1024 CTAs
        fuse2_kernel<<<grd, 256>>>(text, sstruct, mask, gate_b,
                                   enriched, gates);
    }
    ln_kernel<<<T_DIM / 2, 256>>>(enriched, gamma, beta);
}

// round 14
// speedup vs baseline: 1.0310x; 1.0310x over previous
#include <cuda_runtime.h>
#include <cuda_bf16.h>
#include <math.h>
#include <stdint.h>

#define T_DIM 1024
#define S_DIM 128
#define H_DIM 512
#define LN_EPS 1e-5f

#define KSPLIT 1536                 // 3 * 512: hi*hi + hi*lo + lo*hi
#define KCHUNK 64
#define NCHUNKS (KSPLIT / KCHUNK)   // 24
#define MT 64
#define NT 64
#define LDS_STRIDE 72               // bf16 per smem row (64 + 8 pad)
#define NSTAGE 4
#define A_STAGE_ELEMS (MT * LDS_STRIDE)
#define B_STAGE_ELEMS (NT * LDS_STRIDE)
#define SMEM_ELEMS (NSTAGE * (A_STAGE_ELEMS + B_STAGE_ELEMS))
#define SMEM_BYTES (SMEM_ELEMS * 2)

// Scratch (allocation-free rule: __device__ globals)
__device__ float d_gt[T_DIM * H_DIM];
__device__ float d_gs[S_DIM * H_DIM];
__device__ __nv_bfloat16 d_Abf[(T_DIM + S_DIM) * KSPLIT]; // [hi, hi, lo]
__device__ __nv_bfloat16 d_Wt[H_DIM * KSPLIT];            // wt: [hi, lo, hi]
__device__ __nv_bfloat16 d_Ws[H_DIM * KSPLIT];            // ws: [hi, lo, hi]

// ---------------------------------------------------------------------------
// cp.async helpers
// ---------------------------------------------------------------------------
__device__ __forceinline__ void cp_async16(uint32_t dst_smem, const void* src) {
    asm volatile("cp.async.cg.shared.global [%0], [%1], 16;"
                 :: "r"(dst_smem), "l"(src));
}
#define CP_COMMIT() asm volatile("cp.async.commit_group;" ::: "memory")
#define CP_WAIT(n)  asm volatile("cp.async.wait_group %0;" :: "n"(n) : "memory")

// ---------------------------------------------------------------------------
// Merged conversion
// ---------------------------------------------------------------------------
__global__ __launch_bounds__(256) void conv_kernel(
    const float* __restrict__ text, const float* __restrict__ sstruct,
    const float* __restrict__ W)
{
    const int b = blockIdx.x;
    if (b < T_DIM + S_DIM) {
        const int r = b;
        const float* src = (r < T_DIM) ? (text + (size_t)r * H_DIM)
                                       : (sstruct + (size_t)(r - T_DIM) * H_DIM);
        __nv_bfloat16* dst = d_Abf + (size_t)r * KSPLIT;
        for (int j = threadIdx.x; j < KSPLIT; j += 256) {
            int sec = j >> 9;
            int k   = j & 511;
            float x = src[k];
            __nv_bfloat16 h = __float2bfloat16(x);
            dst[j] = (sec == 2) ? __float2bfloat16(x - __bfloat162float(h)) : h;
        }
    } else {
        const int n = b - (T_DIM + S_DIM);
        const float* wrow = W + (size_t)n * 1024;
        __nv_bfloat16* dt = d_Wt + (size_t)n * KSPLIT;
        __nv_bfloat16* ds = d_Ws + (size_t)n * KSPLIT;
        for (int j = threadIdx.x; j < KSPLIT; j += 256) {
            int sec = j >> 9;
            int k   = j & 511;
            {
                float x = wrow[k];
                __nv_bfloat16 h = __float2bfloat16(x);
                dt[j] = (sec == 1) ? __float2bfloat16(x - __bfloat162float(h)) : h;
            }
            {
                float x = wrow[512 + k];
                __nv_bfloat16 h = __float2bfloat16(x);
                ds[j] = (sec == 1) ? __float2bfloat16(x - __bfloat162float(h)) : h;
            }
        }
    }
}

// ---------------------------------------------------------------------------
// HMMA GEMM with 4-deep cp.async ring.
// C[MT x NT] = A'[MT x 1536] @ B'[NT x 1536]^T, fp32 acc.
// 128 threads = 4 warps; warp (wm, wn) owns a 32x32 quadrant.
// Grid: 8 x 18 = 144 CTAs.  Dynamic smem = 73.7 KB.
// ---------------------------------------------------------------------------
__global__ __launch_bounds__(128) void mma_gemm_kernel()
{
    extern __shared__ __nv_bfloat16 smem[];

    const int tid  = threadIdx.x;
    const int wid  = tid >> 5;
    const int lane = tid & 31;
    const int wm   = wid & 1;
    const int wn   = wid >> 1;

    const int bcol  = blockIdx.x * NT;
    const int browg = blockIdx.y * MT;

    const __nv_bfloat16* __restrict__ Bsrc = (browg < T_DIM) ? d_Wt : d_Ws;
    float* __restrict__ C = (browg < T_DIM)
        ? (d_gt + (size_t)browg * H_DIM)
        : (d_gs + (size_t)(browg - T_DIM) * H_DIM);

    float acc[2][4][4];
    #pragma unroll
    for (int i = 0; i < 2; i++)
        #pragma unroll
        for (int j = 0; j < 4; j++)
            #pragma unroll
            for (int q = 0; q < 4; q++) acc[i][j][q] = 0.f;

    // Staging: 2 threads/row, each a contiguous 32-bf16 half-row (4 x 16B)
    const int srow  = tid >> 1;
    const int shalf = (tid & 1) * 32;

    const __nv_bfloat16* Aptr = d_Abf + (size_t)(browg + srow) * KSPLIT + shalf;
    const __nv_bfloat16* Bptr = Bsrc  + (size_t)(bcol  + srow) * KSPLIT + shalf;

    uint32_t sA[NSTAGE], sB[NSTAGE];
    #pragma unroll
    for (int st = 0; st < NSTAGE; st++) {
        sA[st] = (uint32_t)__cvta_generic_to_shared(
            smem + st * A_STAGE_ELEMS + srow * LDS_STRIDE + shalf);
        sB[st] = (uint32_t)__cvta_generic_to_shared(
            smem + NSTAGE * A_STAGE_ELEMS + st * B_STAGE_ELEMS
                 + srow * LDS_STRIDE + shalf);
    }

    // Prologue: prefetch chunks 0..2 into stages 0..2 (one group each)
    #pragma unroll
    for (int p = 0; p < 3; p++) {
        const __nv_bfloat16* ap = Aptr + (size_t)p * KCHUNK;
        const __nv_bfloat16* bp = Bptr + (size_t)p * KCHUNK;
        #pragma unroll
        for (int q = 0; q < 4; q++) {
            cp_async16(sA[p] + q * 16, ap + q * 8);
            cp_async16(sB[p] + q * 16, bp + q * 8);
        }
        CP_COMMIT();
    }

    const int frow = lane >> 2;
    const int fk   = (lane & 3) * 2;

    for (int c = 0; c < NCHUNKS; c++) {
        const int cur = c & (NSTAGE - 1);
        CP_WAIT(2);            // chunk c landed (c+1, c+2 may still be in flight)
        __syncthreads();       // cross-thread visibility of stage 'cur'

        const __nv_bfloat16 (*As)[LDS_STRIDE] =
            (const __nv_bfloat16 (*)[LDS_STRIDE])(smem + cur * A_STAGE_ELEMS);
        const __nv_bfloat16 (*Bs)[LDS_STRIDE] =
            (const __nv_bfloat16 (*)[LDS_STRIDE])(smem + NSTAGE * A_STAGE_ELEMS
                                                  + cur * B_STAGE_ELEMS);

        #pragma unroll
        for (int ks = 0; ks < KCHUNK; ks += 16) {
            uint32_t afr[2][4];
            #pragma unroll
            for (int mi = 0; mi < 2; mi++) {
                const int rb = wm * 32 + mi * 16;
                afr[mi][0] = *(const uint32_t*)&As[rb + frow    ][ks + fk    ];
                afr[mi][1] = *(const uint32_t*)&As[rb + frow + 8][ks + fk    ];
                afr[mi][2] = *(const uint32_t*)&As[rb + frow    ][ks + fk + 8];
                afr[mi][3] = *(const uint32_t*)&As[rb + frow + 8][ks + fk + 8];
            }
            #pragma unroll
            for (int ni = 0; ni < 4; ni++) {
                const int nb = wn * 32 + ni * 8;
                uint32_t b0 = *(const uint32_t*)&Bs[nb + frow][ks + fk    ];
                uint32_t b1 = *(const uint32_t*)&Bs[nb + frow][ks + fk + 8];
                #pragma unroll
                for (int mi = 0; mi < 2; mi++) {
                    asm volatile(
                        "mma.sync.aligned.m16n8k16.row.col.f32.bf16.bf16.f32 "
                        "{%0,%1,%2,%3}, {%4,%5,%6,%7}, {%8,%9}, {%0,%1,%2,%3};"
                        : "+f"(acc[mi][ni][0]), "+f"(acc[mi][ni][1]),
                          "+f"(acc[mi][ni][2]), "+f"(acc[mi][ni][3])
                        : "r"(afr[mi][0]), "r"(afr[mi][1]),
                          "r"(afr[mi][2]), "r"(afr[mi][3]),
                          "r"(b0), "r"(b1));
                }
            }
        }
        __syncthreads();       // readers done before this stage is refilled

        if (c + 3 < NCHUNKS) {
            const int nst = (c + 3) & (NSTAGE - 1);
            const __nv_bfloat16* ap = Aptr + (size_t)(c + 3) * KCHUNK;
            const __nv_bfloat16* bp = Bptr + (size_t)(c + 3) * KCHUNK;
            #pragma unroll
            for (int q = 0; q < 4; q++) {
                cp_async16(sA[nst] + q * 16, ap + q * 8);
                cp_async16(sB[nst] + q * 16, bp + q * 8);
            }
        }
        CP_COMMIT();           // may be an empty group (tail) — keeps counts aligned
    }

    #pragma unroll
    for (int mi = 0; mi < 2; mi++) {
        const int row = wm * 32 + mi * 16 + frow;
        #pragma unroll
        for (int ni = 0; ni < 4; ni++) {
            const int col = bcol + wn * 32 + ni * 8 + fk;
            *(float2*)(C + (size_t)row * H_DIM + col) =
                make_float2(acc[mi][ni][0], acc[mi][ni][1]);
            *(float2*)(C + (size_t)(row + 8) * H_DIM + col) =
                make_float2(acc[mi][ni][2], acc[mi][ni][3]);
        }
    }
}

// ---------------------------------------------------------------------------
// fuse2: store-only hot loop. TT=16, s-split across thread halves.
// Grid (16 h-chunks, 64 t-tiles) = 1024 CTAs, 256 threads, smem 34 KB
// -> 6 CTAs/SM (occ ~75%).
// ---------------------------------------------------------------------------
#define HC 32
#define TT 16

__global__ __launch_bounds__(256) void fuse2_kernel(
    const float* __restrict__ text,
    const float* __restrict__ sstruct,
    const int*   __restrict__ mask,
    const float* __restrict__ gate_b,
    float* __restrict__ xout,
    float* __restrict__ gates)
{
    __shared__ float gs_s[S_DIM][HC];
    __shared__ float st_s[S_DIM][HC];
    __shared__ float part[TT][8][4];

    const int tid = threadIdx.x;
    const int hx  = tid & 7;             // float4 within h-chunk
    const int ts  = (tid >> 3) & 15;     // row 0..15
    const int sh  = tid >> 7;            // 0..1 s-half
    const int h0  = blockIdx.x * HC;
    const int t0  = blockIdx.y * TT;

    #pragma unroll
    for (int i = tid; i < S_DIM * (HC / 4); i += 256) {
        int s  = i >> 3;
        int c4 = (i & 7) * 4;
        *(float4*)&gs_s[s][c4] = *(const float4*)(d_gs    + (size_t)s * H_DIM + h0 + c4);
        *(float4*)&st_s[s][c4] = *(const float4*)(sstruct + (size_t)s * H_DIM + h0 + c4);
    }
    __syncthreads();

    const int h = h0 + hx * 4;
    const int r = t0 + ts;

    const float4 bias = *(const float4*)(gate_b + h);
    float4 gtb;
    {
        float4 a = *(const float4*)(d_gt + (size_t)r * H_DIM + h);
        gtb = make_float4(a.x + bias.x, a.y + bias.y, a.z + bias.z, a.w + bias.w);
    }
    float4 acc = make_float4(0.f, 0.f, 0.f, 0.f);

    const int* __restrict__ mp = mask + (size_t)r * S_DIM;
    float* __restrict__ gp = gates + (size_t)r * S_DIM * H_DIM + h;

    const int s0 = sh * (S_DIM / 2);
    const int s1 = s0 + (S_DIM / 2);
    #pragma unroll 4
    for (int s = s0; s < s1; s++) {
        const float4 gs4 = *(const float4*)&gs_s[s][hx * 4];
        const float4 sv4 = *(const float4*)&st_s[s][hx * 4];
        const bool m = (mp[s] != 0);

        float4 g;
        g.x = m ? fmaxf(gtb.x + gs4.x, 0.f) : 0.f;
        g.y = m ? fmaxf(gtb.y + gs4.y, 0.f) : 0.f;
        g.z = m ? fmaxf(gtb.z + gs4.z, 0.f) : 0.f;
        g.w = m ? fmaxf(gtb.w + gs4.w, 0.f) : 0.f;

        __stcs((float4*)(gp + (size_t)s * H_DIM), g);

        acc.x = fmaf(g.x, sv4.x, acc.x);
        acc.y = fmaf(g.y, sv4.y, acc.y);
        acc.z = fmaf(g.z, sv4.z, acc.z);
        acc.w = fmaf(g.w, sv4.w, acc.w);
    }

    // Combine the two s-half partial enrichments, write x = text + enr.
    if (sh == 1) {
        part[ts][hx][0] = acc.x; part[ts][hx][1] = acc.y;
        part[ts][hx][2] = acc.z; part[ts][hx][3] = acc.w;
    }
    __syncthreads();
    if (sh == 0) {
        float4 t4 = *(const float4*)(text + (size_t)r * H_DIM + h);
        float4 x;
        x.x = t4.x + acc.x + part[ts][hx][0];
        x.y = t4.y + acc.y + part[ts][hx][1];
        x.z = t4.z + acc.z + part[ts][hx][2];
        x.w = t4.w + acc.w + part[ts][hx][3];
        *(float4*)(xout + (size_t)r * H_DIM + h) = x;
    }
}

// ---------------------------------------------------------------------------
// In-place LayerNorm. UNCHANGED.
// ---------------------------------------------------------------------------
__global__ __launch_bounds__(256) void ln_kernel(
    float* __restrict__ x,
    const float* __restrict__ gamma,
    const float* __restrict__ beta)
{
    const int tid = threadIdx.x;
    const int h4  = tid & 127;
    const int tg  = tid >> 7;
    const int h   = h4 * 4;
    const int r   = blockIdx.x * 2 + tg;

    __shared__ float red[2][2][4];

    float4 v = *(const float4*)(x + (size_t)r * H_DIM + h);
    float s1 = v.x + v.y + v.z + v.w;
    float s2 = v.x * v.x + v.y * v.y + v.z * v.z + v.w * v.w;

    const int lane = tid & 31;
    const int wg   = (tid >> 5) & 3;
    #pragma unroll
    for (int o = 16; o > 0; o >>= 1) {
        s1 += __shfl_xor_sync(0xFFFFFFFFu, s1, o);
        s2 += __shfl_xor_sync(0xFFFFFFFFu, s2, o);
    }
    if (lane == 0) { red[0][tg][wg] = s1; red[1][tg][wg] = s2; }
    __syncthreads();

    s1 = red[0][tg][0] + red[0][tg][1] + red[0][tg][2] + red[0][tg][3];
    s2 = red[1][tg][0] + red[1][tg][1] + red[1][tg][2] + red[1][tg][3];
    float mu  = s1 * (1.f / H_DIM);
    float var = s2 * (1.f / H_DIM) - mu * mu;
    float inv = rsqrtf(var + LN_EPS);

    const float4 gm = *(const float4*)(gamma + h);
    const float4 bt = *(const float4*)(beta  + h);
    float4 o;
    o.x = (v.x - mu) * inv * gm.x + bt.x;
    o.y = (v.y - mu) * inv * gm.y + bt.y;
    o.z = (v.z - mu) * inv * gm.z + bt.z;
    o.w = (v.w - mu) * inv * gm.w + bt.w;
    *(float4*)(x + (size_t)r * H_DIM + h) = o;
}

// ---------------------------------------------------------------------------
extern "C" void kernel_launch(void* const* d_in, const int* in_sizes, int n_in,
                              void* d_out, int out_size)
{
    const float* text    = (const float*)d_in[0];
    const float* sstruct = (const float*)d_in[1];
    const int*   mask    = (const int*)  d_in[2];
    const float* gate_w  = (const float*)d_in[3];
    const float* gate_b  = (const float*)d_in[4];
    const float* gamma   = (const float*)d_in[5];
    const float* beta    = (const float*)d_in[6];

    float* enriched = (float*)d_out;
    float* gates    = (float*)d_out + (size_t)T_DIM * H_DIM;

    conv_kernel<<<T_DIM + S_DIM + H_DIM, 256>>>(text, sstruct, gate_w);
    {
        cudaFuncSetAttribute(mma_gemm_kernel,
                             cudaFuncAttributeMaxDynamicSharedMemorySize,
                             SMEM_BYTES);
        dim3 grd(H_DIM / NT, (T_DIM + S_DIM) / MT);   // 8 x 18 = 144 CTAs
        mma_gemm_kernel<<<grd, 128, SMEM_BYTES>>>();
    }
    {
        dim3 grd(H_DIM / HC, T_DIM / TT);             // 16 x 64 = 1024 CTAs
        fuse2_kernel<<<grd, 256>>>(text, sstruct, mask, gate_b,
                                   enriched, gates);
    }
    ln_kernel<<<T_DIM / 2, 256>>>(enriched, gamma, beta);
}

// round 15
// speedup vs baseline: 1.0315x; 1.0004x over previous
#include <cuda_runtime.h>
#include <cuda_bf16.h>
#include <math.h>
#include <stdint.h>

#define T_DIM 1024
#define S_DIM 128
#define H_DIM 512
#define LN_EPS 1e-5f

#define KSPLIT 1536                 // 3 * 512: hi*hi + hi*lo + lo*hi
#define KCHUNK 64
#define NCHUNKS (KSPLIT / KCHUNK)   // 24
#define LDS_STRIDE 72
#define A_ELEMS (64 * LDS_STRIDE)   // per stage, per matrix

#define PROD_CTAS 144               // 18 Mtiles x 8 col tiles
#define HC 32
#define TT 32
#define CONS_CTAS ((H_DIM / HC) * (T_DIM / TT))   // 512
#define MTILES 18

// Scratch (allocation-free rule: __device__ globals)
__device__ float d_gt[T_DIM * H_DIM];
__device__ float d_gs[S_DIM * H_DIM];
__device__ __nv_bfloat16 d_Abf[(T_DIM + S_DIM) * KSPLIT]; // [hi, hi, lo]
__device__ __nv_bfloat16 d_Wt[H_DIM * KSPLIT];            // wt: [hi, lo, hi]
__device__ __nv_bfloat16 d_Ws[H_DIM * KSPLIT];            // ws: [hi, lo, hi]
__device__ unsigned int d_cnt[MTILES];                    // release counters

// ---------------------------------------------------------------------------
// PTX helpers
// ---------------------------------------------------------------------------
__device__ __forceinline__ void cp_async16(uint32_t dst_smem, const void* src) {
    asm volatile("cp.async.cg.shared.global [%0], [%1], 16;"
                 :: "r"(dst_smem), "l"(src));
}
#define CP_COMMIT() asm volatile("cp.async.commit_group;" ::: "memory")
#define CP_WAIT(n)  asm volatile("cp.async.wait_group %0;" :: "n"(n) : "memory")

__device__ __forceinline__ unsigned ld_acq(const unsigned* p) {
    unsigned v;
    asm volatile("ld.acquire.gpu.global.u32 %0, [%1];" : "=r"(v) : "l"(p) : "memory");
    return v;
}
__device__ __forceinline__ void red_release_add(unsigned* p, unsigned v) {
    asm volatile("red.release.gpu.global.add.u32 [%0], %1;" :: "l"(p), "r"(v) : "memory");
}

// ---------------------------------------------------------------------------
// Conversion (unchanged)
// ---------------------------------------------------------------------------
__global__ __launch_bounds__(256) void conv_kernel(
    const float* __restrict__ text, const float* __restrict__ sstruct,
    const float* __restrict__ W)
{
    const int b = blockIdx.x;
    if (b < T_DIM + S_DIM) {
        const int r = b;
        const float* src = (r < T_DIM) ? (text + (size_t)r * H_DIM)
                                       : (sstruct + (size_t)(r - T_DIM) * H_DIM);
        __nv_bfloat16* dst = d_Abf + (size_t)r * KSPLIT;
        for (int j = threadIdx.x; j < KSPLIT; j += 256) {
            int sec = j >> 9;
            int k   = j & 511;
            float x = src[k];
            __nv_bfloat16 h = __float2bfloat16(x);
            dst[j] = (sec == 2) ? __float2bfloat16(x - __bfloat162float(h)) : h;
        }
    } else {
        const int n = b - (T_DIM + S_DIM);
        const float* wrow = W + (size_t)n * 1024;
        __nv_bfloat16* dt = d_Wt + (size_t)n * KSPLIT;
        __nv_bfloat16* ds = d_Ws + (size_t)n * KSPLIT;
        for (int j = threadIdx.x; j < KSPLIT; j += 256) {
            int sec = j >> 9;
            int k   = j & 511;
            {
                float x = wrow[k];
                __nv_bfloat16 h = __float2bfloat16(x);
                dt[j] = (sec == 1) ? __float2bfloat16(x - __bfloat162float(h)) : h;
            }
            {
                float x = wrow[512 + k];
                __nv_bfloat16 h = __float2bfloat16(x);
                ds[j] = (sec == 1) ? __float2bfloat16(x - __bfloat162float(h)) : h;
            }
        }
    }
}

// ---------------------------------------------------------------------------
// Merged producer/consumer kernel.
//  CTAs [0,144):  GEMM producers.  bx<16 -> gs Mtiles 16,17 (early unlock);
//                 bx>=16 -> gt Mtiles 0..15.  64x64 tile, 8 warps, cp.async x2.
//  CTAs [144,656): fuse consumers. ttile = cid/16 (32 rows), hchunk = cid%16.
//                 st-stage -> zero-pass -> spin -> gs-stage -> compute-pass.
// ---------------------------------------------------------------------------
__global__ __launch_bounds__(256) void merged_kernel(
    const float* __restrict__ text,
    const float* __restrict__ sstruct,
    const int*   __restrict__ mask,
    const float* __restrict__ gate_b,
    float* __restrict__ xout,
    float* __restrict__ gates)
{
    __shared__ __align__(16) unsigned char sbuf[4 * A_ELEMS * 2];   // 36864 B

    const int bx  = blockIdx.x;
    const int tid = threadIdx.x;

    if (bx < PROD_CTAS) {
        // ================= PRODUCER =================
        int mtile, bcol;
        if (bx < 16) { mtile = 16 + (bx >> 3); bcol = (bx & 7) * 64; }
        else         { int q = bx - 16; mtile = q >> 3; bcol = (q & 7) * 64; }
        const int browg = mtile * 64;

        const __nv_bfloat16* __restrict__ Bsrc = (mtile < 16) ? d_Wt : d_Ws;
        float* __restrict__ C = (mtile < 16)
            ? (d_gt + (size_t)browg * H_DIM)
            : (d_gs + (size_t)(browg - T_DIM) * H_DIM);

        __nv_bfloat16* smem = (__nv_bfloat16*)sbuf;
        // layout: As stage0, As stage1, Bs stage0, Bs stage1

        const int wid  = tid >> 5;
        const int lane = tid & 31;
        const int wm   = wid & 1;         // M 32-half
        const int wn   = wid >> 1;        // 0..3 -> 16-col quarter

        float acc[2][2][4];
        #pragma unroll
        for (int i = 0; i < 2; i++)
            #pragma unroll
            for (int j = 0; j < 2; j++)
                #pragma unroll
                for (int q = 0; q < 4; q++) acc[i][j][q] = 0.f;

        // staging: tid<128 -> A, tid>=128 -> B; 1 half-row (32 bf16) each
        const int isB   = tid >> 7;
        const int t128  = tid & 127;
        const int srow  = t128 >> 1;
        const int shalf = (t128 & 1) * 32;

        const __nv_bfloat16* gsrc = isB
            ? (Bsrc  + (size_t)(bcol  + srow) * KSPLIT + shalf)
            : (d_Abf + (size_t)(browg + srow) * KSPLIT + shalf);

        uint32_t sdst[2];
        #pragma unroll
        for (int st = 0; st < 2; st++) {
            __nv_bfloat16* base = smem + (isB ? (2 + st) : st) * A_ELEMS
                                       + srow * LDS_STRIDE + shalf;
            sdst[st] = (uint32_t)__cvta_generic_to_shared(base);
        }

        // prologue: chunk 0 -> stage 0
        #pragma unroll
        for (int q = 0; q < 4; q++) cp_async16(sdst[0] + q * 16, gsrc + q * 8);
        CP_COMMIT();

        const int frow = lane >> 2;
        const int fk   = (lane & 3) * 2;

        for (int c = 0; c < NCHUNKS; c++) {
            const int cur = c & 1;
            if (c + 1 < NCHUNKS) {
                const __nv_bfloat16* gp = gsrc + (size_t)(c + 1) * KCHUNK;
                const int nxt = cur ^ 1;
                #pragma unroll
                for (int q = 0; q < 4; q++) cp_async16(sdst[nxt] + q * 16, gp + q * 8);
                CP_COMMIT();
                CP_WAIT(1);
            } else {
                CP_WAIT(0);
            }
            __syncthreads();

            const __nv_bfloat16 (*As)[LDS_STRIDE] =
                (const __nv_bfloat16 (*)[LDS_STRIDE])(smem + cur * A_ELEMS);
            const __nv_bfloat16 (*Bs)[LDS_STRIDE] =
                (const __nv_bfloat16 (*)[LDS_STRIDE])(smem + (2 + cur) * A_ELEMS);

            #pragma unroll
            for (int ks = 0; ks < KCHUNK; ks += 16) {
                uint32_t afr[2][4];
                #pragma unroll
                for (int mi = 0; mi < 2; mi++) {
                    const int rb = wm * 32 + mi * 16;
                    afr[mi][0] = *(const uint32_t*)&As[rb + frow    ][ks + fk    ];
                    afr[mi][1] = *(const uint32_t*)&As[rb + frow + 8][ks + fk    ];
                    afr[mi][2] = *(const uint32_t*)&As[rb + frow    ][ks + fk + 8];
                    afr[mi][3] = *(const uint32_t*)&As[rb + frow + 8][ks + fk + 8];
                }
                #pragma unroll
                for (int ni = 0; ni < 2; ni++) {
                    const int nb = wn * 16 + ni * 8;
                    uint32_t b0 = *(const uint32_t*)&Bs[nb + frow][ks + fk    ];
                    uint32_t b1 = *(const uint32_t*)&Bs[nb + frow][ks + fk + 8];
                    #pragma unroll
                    for (int mi = 0; mi < 2; mi++) {
                        asm volatile(
                            "mma.sync.aligned.m16n8k16.row.col.f32.bf16.bf16.f32 "
                            "{%0,%1,%2,%3}, {%4,%5,%6,%7}, {%8,%9}, {%0,%1,%2,%3};"
                            : "+f"(acc[mi][ni][0]), "+f"(acc[mi][ni][1]),
                              "+f"(acc[mi][ni][2]), "+f"(acc[mi][ni][3])
                            : "r"(afr[mi][0]), "r"(afr[mi][1]),
                              "r"(afr[mi][2]), "r"(afr[mi][3]),
                              "r"(b0), "r"(b1));
                    }
                }
            }
            __syncthreads();
        }

        // epilogue
        #pragma unroll
        for (int mi = 0; mi < 2; mi++) {
            const int row = wm * 32 + mi * 16 + frow;
            #pragma unroll
            for (int ni = 0; ni < 2; ni++) {
                const int col = bcol + wn * 16 + ni * 8 + fk;
                *(float2*)(C + (size_t)row * H_DIM + col) =
                    make_float2(acc[mi][ni][0], acc[mi][ni][1]);
                *(float2*)(C + (size_t)(row + 8) * H_DIM + col) =
                    make_float2(acc[mi][ni][2], acc[mi][ni][3]);
            }
        }

        __threadfence();
        __syncthreads();
        if (tid == 0) red_release_add(&d_cnt[mtile], 1u);

    } else {
        // ================= CONSUMER =================
        const int cid   = bx - PROD_CTAS;
        const int ttile = cid >> 4;          // 0..31
        const int hc    = cid & 15;          // 0..15
        const int t0    = ttile * TT;
        const int h0    = hc * HC;

        float (*gs_s)[HC] = (float (*)[HC])sbuf;
        float (*st_s)[HC] = (float (*)[HC])(sbuf + S_DIM * HC * 4);

        const int hx = tid & 7;
        const int ts = tid >> 3;             // 0..31
        const int h  = h0 + hx * 4;
        const int r  = t0 + ts;

        // stage struct chunk (input-only, no dependency)
        #pragma unroll
        for (int i = tid; i < S_DIM * (HC / 4); i += 256) {
            int s  = i >> 3;
            int c4 = (i & 7) * 4;
            *(float4*)&st_s[s][c4] =
                *(const float4*)(sstruct + (size_t)s * H_DIM + h0 + c4);
        }

        const int* __restrict__ mp = mask + (size_t)r * S_DIM;
        float* __restrict__ gp = gates + (size_t)r * S_DIM * H_DIM + h;

        // zero-pass: masked-0 gates need nothing from the GEMM
        const float4 z4 = make_float4(0.f, 0.f, 0.f, 0.f);
        #pragma unroll 4
        for (int s = 0; s < S_DIM; s++) {
            if (mp[s] == 0) __stcs((float4*)(gp + (size_t)s * H_DIM), z4);
        }

        // spin until gs tiles + this t-tile's gt Mtile are released
        const int gtile = ttile >> 1;
        if (tid == 0) {
            while (ld_acq(&d_cnt[16]) < 8u)    __nanosleep(64);
            while (ld_acq(&d_cnt[17]) < 8u)    __nanosleep(64);
            while (ld_acq(&d_cnt[gtile]) < 8u) __nanosleep(64);
        }
        __syncthreads();

        // stage gs chunk
        #pragma unroll
        for (int i = tid; i < S_DIM * (HC / 4); i += 256) {
            int s  = i >> 3;
            int c4 = (i & 7) * 4;
            *(float4*)&gs_s[s][c4] =
                *(const float4*)(d_gs + (size_t)s * H_DIM + h0 + c4);
        }
        __syncthreads();

        const float4 bias = *(const float4*)(gate_b + h);
        float4 gtb;
        {
            float4 a = *(const float4*)(d_gt + (size_t)r * H_DIM + h);
            gtb = make_float4(a.x + bias.x, a.y + bias.y, a.z + bias.z, a.w + bias.w);
        }
        float4 acc = make_float4(0.f, 0.f, 0.f, 0.f);

        #pragma unroll 4
        for (int s = 0; s < S_DIM; s++) {
            if (mp[s] != 0) {
                const float4 gs4 = *(const float4*)&gs_s[s][hx * 4];
                const float4 sv4 = *(const float4*)&st_s[s][hx * 4];
                float4 g;
                g.x = fmaxf(gtb.x + gs4.x, 0.f);
                g.y = fmaxf(gtb.y + gs4.y, 0.f);
                g.z = fmaxf(gtb.z + gs4.z, 0.f);
                g.w = fmaxf(gtb.w + gs4.w, 0.f);
                __stcs((float4*)(gp + (size_t)s * H_DIM), g);
                acc.x = fmaf(g.x, sv4.x, acc.x);
                acc.y = fmaf(g.y, sv4.y, acc.y);
                acc.z = fmaf(g.z, sv4.z, acc.z);
                acc.w = fmaf(g.w, sv4.w, acc.w);
            }
        }

        {
            float4 t4 = *(const float4*)(text + (size_t)r * H_DIM + h);
            *(float4*)(xout + (size_t)r * H_DIM + h) =
                make_float4(t4.x + acc.x, t4.y + acc.y, t4.z + acc.z, t4.w + acc.w);
        }
    }
}

// ---------------------------------------------------------------------------
// In-place LayerNorm. UNCHANGED.
// ---------------------------------------------------------------------------
__global__ __launch_bounds__(256) void ln_kernel(
    float* __restrict__ x,
    const float* __restrict__ gamma,
    const float* __restrict__ beta)
{
    const int tid = threadIdx.x;
    const int h4  = tid & 127;
    const int tg  = tid >> 7;
    const int h   = h4 * 4;
    const int r   = blockIdx.x * 2 + tg;

    __shared__ float red[2][2][4];

    float4 v = *(const float4*)(x + (size_t)r * H_DIM + h);
    float s1 = v.x + v.y + v.z + v.w;
    float s2 = v.x * v.x + v.y * v.y + v.z * v.z + v.w * v.w;

    const int lane = tid & 31;
    const int wg   = (tid >> 5) & 3;
    #pragma unroll
    for (int o = 16; o > 0; o >>= 1) {
        s1 += __shfl_xor_sync(0xFFFFFFFFu, s1, o);
        s2 += __shfl_xor_sync(0xFFFFFFFFu, s2, o);
    }
    if (lane == 0) { red[0][tg][wg] = s1; red[1][tg][wg] = s2; }
    __syncthreads();

    s1 = red[0][tg][0] + red[0][tg][1] + red[0][tg][2] + red[0][tg][3];
    s2 = red[1][tg][0] + red[1][tg][1] + red[1][tg][2] + red[1][tg][3];
    float mu  = s1 * (1.f / H_DIM);
    float var = s2 * (1.f / H_DIM) - mu * mu;
    float inv = rsqrtf(var + LN_EPS);

    const float4 gm = *(const float4*)(gamma + h);
    const float4 bt = *(const float4*)(beta  + h);
    float4 o;
    o.x = (v.x - mu) * inv * gm.x + bt.x;
    o.y = (v.y - mu) * inv * gm.y + bt.y;
    o.z = (v.z - mu) * inv * gm.z + bt.z;
    o.w = (v.w - mu) * inv * gm.w + bt.w;
    *(float4*)(x + (size_t)r * H_DIM + h) = o;
}

// ---------------------------------------------------------------------------
extern "C" void kernel_launch(void* const* d_in, const int* in_sizes, int n_in,
                              void* d_out, int out_size)
{
    const float* text    = (const float*)d_in[0];
    const float* sstruct = (const float*)d_in[1];
    const int*   mask    = (const int*)  d_in[2];
    const float* gate_w  = (const float*)d_in[3];
    const float* gate_b  = (const float*)d_in[4];
    const float* gamma   = (const float*)d_in[5];
    const float* beta    = (const float*)d_in[6];

    float* enriched = (float*)d_out;
    float* gates    = (float*)d_out + (size_t)T_DIM * H_DIM;

    conv_kernel<<<T_DIM + S_DIM + H_DIM, 256>>>(text, sstruct, gate_w);
    merged_kernel<<<PROD_CTAS + CONS_CTAS, 256>>>(text, sstruct, mask, gate_b,
                                                  enriched, gates);
    ln_kernel<<<T_DIM / 2, 256>>>(enriched, gamma, beta);
}

// round 16
// speedup vs baseline: 1.0912x; 1.0579x over previous
#include <cuda_runtime.h>
#include <cuda_bf16.h>
#include <math.h>
#include <stdint.h>

#define T_DIM 1024
#define S_DIM 128
#define H_DIM 512
#define LN_EPS 1e-5f

#define NCHUNKS 24                  // virtual K = 1536 over dedup storage 1024
#define KCHUNK 64
#define LDS_STRIDE 72
#define A_ELEMS (64 * LDS_STRIDE)

#define PROD_CTAS 144
#define HC 32
#define TT 32
#define CONS_CTAS ((H_DIM / HC) * (T_DIM / TT))   // 512
#define MTILES 18

// Scratch (allocation-free rule: __device__ globals). Dedup: [hi(512), lo(512)]
__device__ float d_gt[T_DIM * H_DIM];
__device__ float d_gs[S_DIM * H_DIM];
__device__ __nv_bfloat16 d_A2[(T_DIM + S_DIM) * 1024];
__device__ __nv_bfloat16 d_Wt2[H_DIM * 1024];
__device__ __nv_bfloat16 d_Ws2[H_DIM * 1024];
__device__ unsigned int d_cnt[MTILES];

// ---------------------------------------------------------------------------
// PTX helpers
// ---------------------------------------------------------------------------
__device__ __forceinline__ void cp_async16(uint32_t dst_smem, const void* src) {
    asm volatile("cp.async.cg.shared.global [%0], [%1], 16;"
                 :: "r"(dst_smem), "l"(src));
}
#define CP_COMMIT() asm volatile("cp.async.commit_group;" ::: "memory")
#define CP_WAIT(n)  asm volatile("cp.async.wait_group %0;" :: "n"(n) : "memory")

__device__ __forceinline__ unsigned ld_acq(const unsigned* p) {
    unsigned v;
    asm volatile("ld.acquire.gpu.global.u32 %0, [%1];" : "=r"(v) : "l"(p) : "memory");
    return v;
}
__device__ __forceinline__ void red_release_add(unsigned* p, unsigned v) {
    asm volatile("red.release.gpu.global.add.u32 [%0], %1;" :: "l"(p), "r"(v) : "memory");
}
__device__ __forceinline__ uint32_t bfpack2(float a, float b) {
    __nv_bfloat162 t = __floats2bfloat162_rn(a, b);
    return *reinterpret_cast<uint32_t*>(&t);
}
__device__ __forceinline__ float bflo(float x) {
    return x - __bfloat162float(__float2bfloat16(x));
}

// Virtual chunk c (0..23) -> element offset in dedup [hi,lo] storage.
// A sections: [hi, hi, lo];  W sections: [hi, lo, hi]
__device__ __forceinline__ int chunk_off_A(int c) {
    return (c < 8) ? c * 64 : (c < 16) ? (c - 8) * 64 : 512 + (c - 16) * 64;
}
__device__ __forceinline__ int chunk_off_W(int c) {
    return (c < 8) ? c * 64 : (c < 16) ? 512 + (c - 8) * 64 : (c - 16) * 64;
}

// ---------------------------------------------------------------------------
// Vectorized dedup conversion: float4 loads, uint2 packed-bf16 stores.
// ---------------------------------------------------------------------------
#define A_QUADS ((T_DIM + S_DIM) * (H_DIM / 4))   // 147456
#define W_QUADS (H_DIM * (1024 / 4))              // 131072

__global__ __launch_bounds__(256) void conv_kernel(
    const float* __restrict__ text, const float* __restrict__ sstruct,
    const float* __restrict__ W)
{
    const int stride = gridDim.x * 256;
    for (int q = blockIdx.x * 256 + threadIdx.x; q < A_QUADS + W_QUADS; q += stride) {
        if (q < A_QUADS) {
            const int row = q >> 7;
            const int c   = (q & 127) * 4;
            const float* src = (row < T_DIM)
                ? (text + (size_t)row * H_DIM + c)
                : (sstruct + (size_t)(row - T_DIM) * H_DIM + c);
            float4 v = *(const float4*)src;
            __nv_bfloat16* dst = d_A2 + (size_t)row * 1024 + c;
            *(uint2*)dst = make_uint2(bfpack2(v.x, v.y), bfpack2(v.z, v.w));
            *(uint2*)(dst + 512) = make_uint2(bfpack2(bflo(v.x), bflo(v.y)),
                                              bfpack2(bflo(v.z), bflo(v.w)));
        } else {
            const int q2  = q - A_QUADS;
            const int row = q2 >> 8;
            const int cc  = (q2 & 255) * 4;       // 0..1020
            const int half = cc >> 9;             // 0 = wt, 1 = ws
            const int c    = cc & 511;
            float4 v = *(const float4*)(W + (size_t)row * 1024 + cc);
            __nv_bfloat16* dst = (half ? d_Ws2 : d_Wt2) + (size_t)row * 1024 + c;
            *(uint2*)dst = make_uint2(bfpack2(v.x, v.y), bfpack2(v.z, v.w));
            *(uint2*)(dst + 512) = make_uint2(bfpack2(bflo(v.x), bflo(v.y)),
                                              bfpack2(bflo(v.z), bflo(v.w)));
        }
    }
}

// ---------------------------------------------------------------------------
// Merged producer/consumer kernel (R15 structure, ldmatrix producers).
// ---------------------------------------------------------------------------
__global__ __launch_bounds__(256) void merged_kernel(
    const float* __restrict__ text,
    const float* __restrict__ sstruct,
    const int*   __restrict__ mask,
    const float* __restrict__ gate_b,
    float* __restrict__ xout,
    float* __restrict__ gates)
{
    __shared__ __align__(16) unsigned char sbuf[4 * A_ELEMS * 2];   // 36864 B

    const int bx  = blockIdx.x;
    const int tid = threadIdx.x;

    if (bx < PROD_CTAS) {
        // ================= PRODUCER =================
        int mtile, bcol;
        if (bx < 16) { mtile = 16 + (bx >> 3); bcol = (bx & 7) * 64; }
        else         { int q = bx - 16; mtile = q >> 3; bcol = (q & 7) * 64; }
        const int browg = mtile * 64;

        const __nv_bfloat16* __restrict__ Bsrc = (mtile < 16) ? d_Wt2 : d_Ws2;
        float* __restrict__ C = (mtile < 16)
            ? (d_gt + (size_t)browg * H_DIM)
            : (d_gs + (size_t)(browg - T_DIM) * H_DIM);

        __nv_bfloat16* smem = (__nv_bfloat16*)sbuf;
        const uint32_t smem_u32 = (uint32_t)__cvta_generic_to_shared(smem);

        const int wid  = tid >> 5;
        const int lane = tid & 31;
        const int wm   = wid & 1;
        const int wn   = wid >> 1;

        float acc[2][2][4];
        #pragma unroll
        for (int i = 0; i < 2; i++)
            #pragma unroll
            for (int j = 0; j < 2; j++)
                #pragma unroll
                for (int q = 0; q < 4; q++) acc[i][j][q] = 0.f;

        // staging: tid<128 -> A, tid>=128 -> B; 1 half-row (32 bf16) each
        const int isB   = tid >> 7;
        const int t128  = tid & 127;
        const int srow  = t128 >> 1;
        const int shalf = (t128 & 1) * 32;

        const __nv_bfloat16* grow = isB
            ? (Bsrc + (size_t)(bcol  + srow) * 1024 + shalf)
            : (d_A2 + (size_t)(browg + srow) * 1024 + shalf);

        uint32_t sdst[2];
        #pragma unroll
        for (int st = 0; st < 2; st++) {
            sdst[st] = smem_u32 + ((isB ? (2 + st) : st) * A_ELEMS
                                   + srow * LDS_STRIDE + shalf) * 2;
        }

        // prologue: chunk 0 -> stage 0
        {
            const __nv_bfloat16* gp = grow + (isB ? chunk_off_W(0) : chunk_off_A(0));
            #pragma unroll
            for (int q = 0; q < 4; q++) cp_async16(sdst[0] + q * 16, gp + q * 8);
            CP_COMMIT();
        }

        // ldmatrix lane-address components
        const int arow_l = (lane & 7) + ((lane >> 3) & 1) * 8;
        const int ak_l   = (lane >> 4) * 8;
        const int brow_l = lane & 7;
        const int bk_l   = ((lane >> 3) & 1) * 8;

        for (int c = 0; c < NCHUNKS; c++) {
            const int cur = c & 1;
            if (c + 1 < NCHUNKS) {
                const __nv_bfloat16* gp = grow +
                    (isB ? chunk_off_W(c + 1) : chunk_off_A(c + 1));
                const int nxt = cur ^ 1;
                #pragma unroll
                for (int q = 0; q < 4; q++) cp_async16(sdst[nxt] + q * 16, gp + q * 8);
                CP_COMMIT();
                CP_WAIT(1);
            } else {
                CP_WAIT(0);
            }
            __syncthreads();

            const uint32_t Abase = smem_u32 + (cur * A_ELEMS) * 2;
            const uint32_t Bbase = smem_u32 + ((2 + cur) * A_ELEMS) * 2;

            #pragma unroll
            for (int ks = 0; ks < KCHUNK; ks += 16) {
                uint32_t afr[2][4];
                #pragma unroll
                for (int mi = 0; mi < 2; mi++) {
                    const int rb = wm * 32 + mi * 16;
                    uint32_t addr = Abase +
                        ((rb + arow_l) * LDS_STRIDE + ks + ak_l) * 2;
                    asm volatile(
                        "ldmatrix.sync.aligned.m8n8.x4.shared.b16 {%0,%1,%2,%3}, [%4];"
                        : "=r"(afr[mi][0]), "=r"(afr[mi][1]),
                          "=r"(afr[mi][2]), "=r"(afr[mi][3])
                        : "r"(addr));
                }
                #pragma unroll
                for (int ni = 0; ni < 2; ni++) {
                    const int nb = wn * 16 + ni * 8;
                    uint32_t baddr = Bbase +
                        ((nb + brow_l) * LDS_STRIDE + ks + bk_l) * 2;
                    uint32_t b0, b1;
                    asm volatile(
                        "ldmatrix.sync.aligned.m8n8.x2.shared.b16 {%0,%1}, [%2];"
                        : "=r"(b0), "=r"(b1) : "r"(baddr));
                    #pragma unroll
                    for (int mi = 0; mi < 2; mi++) {
                        asm volatile(
                            "mma.sync.aligned.m16n8k16.row.col.f32.bf16.bf16.f32 "
                            "{%0,%1,%2,%3}, {%4,%5,%6,%7}, {%8,%9}, {%0,%1,%2,%3};"
                            : "+f"(acc[mi][ni][0]), "+f"(acc[mi][ni][1]),
                              "+f"(acc[mi][ni][2]), "+f"(acc[mi][ni][3])
                            : "r"(afr[mi][0]), "r"(afr[mi][1]),
                              "r"(afr[mi][2]), "r"(afr[mi][3]),
                              "r"(b0), "r"(b1));
                    }
                }
            }
            __syncthreads();
        }

        const int frow = lane >> 2;
        const int fk   = (lane & 3) * 2;
        #pragma unroll
        for (int mi = 0; mi < 2; mi++) {
            const int row = wm * 32 + mi * 16 + frow;
            #pragma unroll
            for (int ni = 0; ni < 2; ni++) {
                const int col = bcol + wn * 16 + ni * 8 + fk;
                *(float2*)(C + (size_t)row * H_DIM + col) =
                    make_float2(acc[mi][ni][0], acc[mi][ni][1]);
                *(float2*)(C + (size_t)(row + 8) * H_DIM + col) =
                    make_float2(acc[mi][ni][2], acc[mi][ni][3]);
            }
        }

        __threadfence();
        __syncthreads();
        if (tid == 0) red_release_add(&d_cnt[mtile], 1u);

    } else {
        // ================= CONSUMER =================
        const int cid   = bx - PROD_CTAS;
        const int ttile = cid >> 4;
        const int hc    = cid & 15;
        const int t0    = ttile * TT;
        const int h0    = hc * HC;

        float (*gs_s)[HC] = (float (*)[HC])sbuf;
        float (*st_s)[HC] = (float (*)[HC])(sbuf + S_DIM * HC * 4);

        const int hx = tid & 7;
        const int ts = tid >> 3;
        const int h  = h0 + hx * 4;
        const int r  = t0 + ts;

        #pragma unroll
        for (int i = tid; i < S_DIM * (HC / 4); i += 256) {
            int s  = i >> 3;
            int c4 = (i & 7) * 4;
            *(float4*)&st_s[s][c4] =
                *(const float4*)(sstruct + (size_t)s * H_DIM + h0 + c4);
        }

        const int* __restrict__ mp = mask + (size_t)r * S_DIM;
        float* __restrict__ gp = gates + (size_t)r * S_DIM * H_DIM + h;

        // zero-pass: masked-0 gates need nothing from the GEMM
        const float4 z4 = make_float4(0.f, 0.f, 0.f, 0.f);
        #pragma unroll 4
        for (int s = 0; s < S_DIM; s++) {
            if (mp[s] == 0) __stcs((float4*)(gp + (size_t)s * H_DIM), z4);
        }

        const int gtile = ttile >> 1;
        if (tid == 0) {
            while (ld_acq(&d_cnt[16]) < 8u)    __nanosleep(64);
            while (ld_acq(&d_cnt[17]) < 8u)    __nanosleep(64);
            while (ld_acq(&d_cnt[gtile]) < 8u) __nanosleep(64);
        }
        __syncthreads();

        #pragma unroll
        for (int i = tid; i < S_DIM * (HC / 4); i += 256) {
            int s  = i >> 3;
            int c4 = (i & 7) * 4;
            *(float4*)&gs_s[s][c4] =
                *(const float4*)(d_gs + (size_t)s * H_DIM + h0 + c4);
        }
        __syncthreads();

        const float4 bias = *(const float4*)(gate_b + h);
        float4 gtb;
        {
            float4 a = *(const float4*)(d_gt + (size_t)r * H_DIM + h);
            gtb = make_float4(a.x + bias.x, a.y + bias.y, a.z + bias.z, a.w + bias.w);
        }
        float4 acc = make_float4(0.f, 0.f, 0.f, 0.f);

        #pragma unroll 4
        for (int s = 0; s < S_DIM; s++) {
            if (mp[s] != 0) {
                const float4 gs4 = *(const float4*)&gs_s[s][hx * 4];
                const float4 sv4 = *(const float4*)&st_s[s][hx * 4];
                float4 g;
                g.x = fmaxf(gtb.x + gs4.x, 0.f);
                g.y = fmaxf(gtb.y + gs4.y, 0.f);
                g.z = fmaxf(gtb.z + gs4.z, 0.f);
                g.w = fmaxf(gtb.w + gs4.w, 0.f);
                __stcs((float4*)(gp + (size_t)s * H_DIM), g);
                acc.x = fmaf(g.x, sv4.x, acc.x);
                acc.y = fmaf(g.y, sv4.y, acc.y);
                acc.z = fmaf(g.z, sv4.z, acc.z);
                acc.w = fmaf(g.w, sv4.w, acc.w);
            }
        }

        {
            float4 t4 = *(const float4*)(text + (size_t)r * H_DIM + h);
            *(float4*)(xout + (size_t)r * H_DIM + h) =
                make_float4(t4.x + acc.x, t4.y + acc.y, t4.z + acc.z, t4.w + acc.w);
        }
    }
}

// ---------------------------------------------------------------------------
// In-place LayerNorm. UNCHANGED.
// ---------------------------------------------------------------------------
__global__ __launch_bounds__(256) void ln_kernel(
    float* __restrict__ x,
    const float* __restrict__ gamma,
    const float* __restrict__ beta)
{
    const int tid = threadIdx.x;
    const int h4  = tid & 127;
    const int tg  = tid >> 7;
    const int h   = h4 * 4;
    const int r   = blockIdx.x * 2 + tg;

    __shared__ float red[2][2][4];

    float4 v = *(const float4*)(x + (size_t)r * H_DIM + h);
    float s1 = v.x + v.y + v.z + v.w;
    float s2 = v.x * v.x + v.y * v.y + v.z * v.z + v.w * v.w;

    const int lane = tid & 31;
    const int wg   = (tid >> 5) & 3;
    #pragma unroll
    for (int o = 16; o > 0; o >>= 1) {
        s1 += __shfl_xor_sync(0xFFFFFFFFu, s1, o);
        s2 += __shfl_xor_sync(0xFFFFFFFFu, s2, o);
    }
    if (lane == 0) { red[0][tg][wg] = s1; red[1][tg][wg] = s2; }
    __syncthreads();

    s1 = red[0][tg][0] + red[0][tg][1] + red[0][tg][2] + red[0][tg][3];
    s2 = red[1][tg][0] + red[1][tg][1] + red[1][tg][2] + red[1][tg][3];
    float mu  = s1 * (1.f / H_DIM);
    float var = s2 * (1.f / H_DIM) - mu * mu;
    float inv = rsqrtf(var + LN_EPS);

    const float4 gm = *(const float4*)(gamma + h);
    const float4 bt = *(const float4*)(beta  + h);
    float4 o;
    o.x = (v.x - mu) * inv * gm.x + bt.x;
    o.y = (v.y - mu) * inv * gm.y + bt.y;
    o.z = (v.z - mu) * inv * gm.z + bt.z;
    o.w = (v.w - mu) * inv * gm.w + bt.w;
    *(float4*)(x + (size_t)r * H_DIM + h) = o;
}

// ---------------------------------------------------------------------------
extern "C" void kernel_launch(void* const* d_in, const int* in_sizes, int n_in,
                              void* d_out, int out_size)
{
    const float* text    = (const float*)d_in[0];
    const float* sstruct = (const float*)d_in[1];
    const int*   mask    = (const int*)  d_in[2];
    const float* gate_w  = (const float*)d_in[3];
    const float* gate_b  = (const float*)d_in[4];
    const float* gamma   = (const float*)d_in[5];
    const float* beta    = (const float*)d_in[6];

    float* enriched = (float*)d_out;
    float* gates    = (float*)d_out + (size_t)T_DIM * H_DIM;

    conv_kernel<<<1024, 256>>>(text, sstruct, gate_w);
    merged_kernel<<<PROD_CTAS + CONS_CTAS, 256>>>(text, sstruct, mask, gate_b,
                                                  enriched, gates);
    ln_kernel<<<T_DIM / 2, 256>>>(enriched, gamma, beta);
}